// round 1
// baseline (speedup 1.0000x reference)
#include <cuda_runtime.h>

#define N_STRUCT_MAX 16384

__device__ float g_cinv[N_STRUCT_MAX * 9];
__device__ float g_cvec[N_STRUCT_MAX * 32];

__device__ __forceinline__ float leaky(float x) { return x >= 0.f ? x : 0.01f * x; }

__global__ void zero_kernel(float* out, int n) {
    int i = blockIdx.x * blockDim.x + threadIdx.x;
    if (i < n) out[i] = 0.f;
}

// Per-structure: 3x3 inverse + cvec[32] = b2a + w2a[:,9:90] @ outer(cell,cell).ravel()
__global__ void precompute_kernel(const float* __restrict__ cell,
                                  const float* __restrict__ w2a,
                                  const float* __restrict__ b2a,
                                  int S)
{
    int s = blockIdx.x * blockDim.x + threadIdx.x;
    if (s >= S) return;
    float m[9];
#pragma unroll
    for (int i = 0; i < 9; i++) m[i] = cell[s * 9 + i];

    float c00 = m[4] * m[8] - m[5] * m[7];
    float c01 = m[5] * m[6] - m[3] * m[8];
    float c02 = m[3] * m[7] - m[4] * m[6];
    float det = m[0] * c00 + m[1] * c01 + m[2] * c02;
    float id = 1.f / det;
    float inv[9];
    inv[0] = c00 * id;
    inv[1] = (m[2] * m[7] - m[1] * m[8]) * id;
    inv[2] = (m[1] * m[5] - m[2] * m[4]) * id;
    inv[3] = c01 * id;
    inv[4] = (m[0] * m[8] - m[2] * m[6]) * id;
    inv[5] = (m[2] * m[3] - m[0] * m[5]) * id;
    inv[6] = c02 * id;
    inv[7] = (m[1] * m[6] - m[0] * m[7]) * id;
    inv[8] = (m[0] * m[4] - m[1] * m[3]) * id;
#pragma unroll
    for (int i = 0; i < 9; i++) g_cinv[s * 9 + i] = inv[i];

    // cvec[j] = b2a[j] + sum_{p,q} w2a[j][9 + p*9 + q] * m[p]*m[q]
    for (int j = 0; j < 32; j++) {
        float acc = b2a[j];
        const float* wr = w2a + j * 90 + 9;
#pragma unroll
        for (int p = 0; p < 9; p++) {
            float mp = m[p];
#pragma unroll
            for (int q = 0; q < 9; q++)
                acc = fmaf(wr[p * 9 + q], mp * m[q], acc);
        }
        g_cvec[s * 32 + j] = acc;
    }
}

__global__ __launch_bounds__(256) void atom_kernel(
    const float* __restrict__ atom_prop, const float* __restrict__ pos,
    const int* __restrict__ batch,
    const float* __restrict__ w0, const float* __restrict__ b0,
    const float* __restrict__ w1, const float* __restrict__ b1,
    const float* __restrict__ w1n, const float* __restrict__ b1n,
    const float* __restrict__ w2a,
    const float* __restrict__ w2b, const float* __restrict__ b2b,
    const float* __restrict__ w2c, const float* __restrict__ b2c,
    float* __restrict__ out, int n)
{
    __shared__ float sW9[288];   // w2a[:, 0:9]  (32 x 9)
    __shared__ float sW2b[512];  // 16 x 32
    __shared__ float sW2c[96];   // 6 x 16
    __shared__ float sSmall[58]; // w0[9] w1[9] w1n[9] b0[3] b1[3] b1n[3] b2b[16] b2c[6]

    int tid = threadIdx.x;
    for (int i = tid; i < 288; i += blockDim.x) sW9[i] = w2a[(i / 9) * 90 + (i % 9)];
    for (int i = tid; i < 512; i += blockDim.x) sW2b[i] = w2b[i];
    for (int i = tid; i < 96;  i += blockDim.x) sW2c[i] = w2c[i];
    if (tid < 9)        sSmall[tid] = w0[tid];
    else if (tid < 18)  sSmall[tid] = w1[tid - 9];
    else if (tid < 27)  sSmall[tid] = w1n[tid - 18];
    else if (tid < 30)  sSmall[tid] = b0[tid - 27];
    else if (tid < 33)  sSmall[tid] = b1[tid - 30];
    else if (tid < 36)  sSmall[tid] = b1n[tid - 33];
    else if (tid < 52)  sSmall[tid] = b2b[tid - 36];
    else if (tid < 58)  sSmall[tid] = b2c[tid - 52];
    __syncthreads();

    const float* sw0  = sSmall;
    const float* sw1  = sSmall + 9;
    const float* sw1n = sSmall + 18;
    const float* sb0  = sSmall + 27;
    const float* sb1  = sSmall + 30;
    const float* sb1n = sSmall + 33;
    const float* sb2b = sSmall + 36;
    const float* sb2c = sSmall + 52;

    int i = blockIdx.x * blockDim.x + tid;
    int lane = tid & 31;
    bool valid = i < n;
    int b = -1;
    float h3[6];
#pragma unroll
    for (int k = 0; k < 6; k++) h3[k] = 0.f;

    if (valid) {
        b = batch[i];
        float p0 = pos[3 * i], p1 = pos[3 * i + 1], p2 = pos[3 * i + 2];
        const float* ci = g_cinv + b * 9;
        float th[3];
#pragma unroll
        for (int e = 0; e < 3; e++) {
            // frac[e] = sum_d pos[d] * cinv[d][e]
            float f = fmaf(p0, ci[e], fmaf(p1, ci[3 + e], p2 * ci[6 + e]));
            th[e] = f - floorf(f) - 0.5f;
        }
        float ap0 = atom_prop[3 * i], ap1 = atom_prop[3 * i + 1], ap2 = atom_prop[3 * i + 2];

        float x[9];
        x[0] = ap0; x[1] = ap1; x[2] = ap2;
#pragma unroll
        for (int j = 0; j < 3; j++) {
            float a = leaky(fmaf(sw0[j * 3], ap0, fmaf(sw0[j * 3 + 1], ap1, fmaf(sw0[j * 3 + 2], ap2, sb0[j]))));
            float u = fmaf(sw1[j * 3], th[0], fmaf(sw1[j * 3 + 1], th[1], fmaf(sw1[j * 3 + 2], th[2], sb1[j])));
            float v = sb1n[j] - fmaf(sw1n[j * 3], th[0], fmaf(sw1n[j * 3 + 1], th[1], sw1n[j * 3 + 2] * th[2]));
            x[3 + j] = fmaxf(u, 0.f) * a;
            x[6 + j] = fmaxf(v, 0.f) * a;
        }

        const float* cv = g_cvec + b * 32;
        float h1[32];
#pragma unroll
        for (int j = 0; j < 32; j++) {
            float acc = cv[j];
#pragma unroll
            for (int k = 0; k < 9; k++) acc = fmaf(sW9[j * 9 + k], x[k], acc);
            h1[j] = fmaxf(acc, 0.f);
        }
        float h2[16];
#pragma unroll
        for (int j = 0; j < 16; j++) {
            float acc = sb2b[j];
#pragma unroll
            for (int k = 0; k < 32; k++) acc = fmaf(sW2b[j * 32 + k], h1[k], acc);
            h2[j] = leaky(acc);
        }
#pragma unroll
        for (int j = 0; j < 6; j++) {
            float acc = sb2c[j];
#pragma unroll
            for (int k = 0; k < 16; k++) acc = fmaf(sW2c[j * 16 + k], h2[k], acc);
            h3[j] = acc;
        }
    }

    // Segmented inclusive scan over sorted batch within the warp.
    const unsigned mask = 0xffffffffu;
#pragma unroll
    for (int d = 1; d < 32; d <<= 1) {
        int ob = __shfl_up_sync(mask, b, d);
        bool take = (lane >= d) && (ob == b);
#pragma unroll
        for (int k = 0; k < 6; k++) {
            float o = __shfl_up_sync(mask, h3[k], d);
            if (take) h3[k] += o;
        }
    }
    int nb = __shfl_down_sync(mask, b, 1);
    bool tail = (lane == 31) || (nb != b);
    if (valid && tail) {
#pragma unroll
        for (int k = 0; k < 6; k++) atomicAdd(&out[b * 6 + k], h3[k]);
    }
}

extern "C" void kernel_launch(void* const* d_in, const int* in_sizes, int n_in,
                              void* d_out, int out_size)
{
    const float* atom_prop = (const float*)d_in[0];
    const float* pos       = (const float*)d_in[1];
    const float* cell      = (const float*)d_in[2];
    const int*   batch     = (const int*)d_in[3];
    const float* w0  = (const float*)d_in[4];
    const float* b0  = (const float*)d_in[5];
    const float* w1  = (const float*)d_in[6];
    const float* b1  = (const float*)d_in[7];
    const float* w1n = (const float*)d_in[8];
    const float* b1n = (const float*)d_in[9];
    const float* w2a = (const float*)d_in[10];
    const float* b2a = (const float*)d_in[11];
    const float* w2b = (const float*)d_in[12];
    const float* b2b = (const float*)d_in[13];
    const float* w2c = (const float*)d_in[14];
    const float* b2c = (const float*)d_in[15];
    float* out = (float*)d_out;

    int n = in_sizes[3];        // N_ATOMS
    int S = in_sizes[2] / 9;    // N_STRUCT

    zero_kernel<<<(out_size + 255) / 256, 256>>>(out, out_size);
    precompute_kernel<<<(S + 255) / 256, 256>>>(cell, w2a, b2a, S);
    atom_kernel<<<(n + 255) / 256, 256>>>(atom_prop, pos, batch,
                                          w0, b0, w1, b1, w1n, b1n,
                                          w2a, w2b, b2b, w2c, b2c,
                                          out, n);
}

// round 2
// speedup vs baseline: 1.1467x; 1.1467x over previous
#include <cuda_runtime.h>

#define N_STRUCT_MAX 16384

__device__ __align__(16) float g_cinv[N_STRUCT_MAX * 12];  // 3x3 inverse, padded to 12
__device__ __align__(16) float g_cvec[N_STRUCT_MAX * 32];  // b2a + w2a[:,9:90] @ cellouter

__device__ __forceinline__ float leaky(float x) { return x >= 0.f ? x : 0.01f * x; }

__device__ __forceinline__ unsigned long long pack2(float lo, float hi) {
    unsigned long long r;
    asm("mov.b64 %0, {%1, %2};" : "=l"(r) : "f"(lo), "f"(hi));
    return r;
}
__device__ __forceinline__ void unpack2(unsigned long long v, float& lo, float& hi) {
    asm("mov.b64 {%0, %1}, %2;" : "=f"(lo), "=f"(hi) : "l"(v));
}
__device__ __forceinline__ unsigned long long fma2(unsigned long long a, unsigned long long b,
                                                   unsigned long long c) {
    unsigned long long d;
    asm("fma.rn.f32x2 %0, %1, %2, %3;" : "=l"(d) : "l"(a), "l"(b), "l"(c));
    return d;
}

// Per-structure: zero out[6s..6s+5], 3x3 inverse, cvec[32].
__global__ void precompute_kernel(const float* __restrict__ cell,
                                  const float* __restrict__ w2a,
                                  const float* __restrict__ b2a,
                                  float* __restrict__ out, int S)
{
    int s = blockIdx.x * blockDim.x + threadIdx.x;
    if (s >= S) return;

#pragma unroll
    for (int k = 0; k < 6; k++) out[s * 6 + k] = 0.f;

    float m[9];
#pragma unroll
    for (int i = 0; i < 9; i++) m[i] = cell[s * 9 + i];

    float c00 = m[4] * m[8] - m[5] * m[7];
    float c01 = m[5] * m[6] - m[3] * m[8];
    float c02 = m[3] * m[7] - m[4] * m[6];
    float det = m[0] * c00 + m[1] * c01 + m[2] * c02;
    float id = 1.f / det;
    float inv[9];
    inv[0] = c00 * id;
    inv[1] = (m[2] * m[7] - m[1] * m[8]) * id;
    inv[2] = (m[1] * m[5] - m[2] * m[4]) * id;
    inv[3] = c01 * id;
    inv[4] = (m[0] * m[8] - m[2] * m[6]) * id;
    inv[5] = (m[2] * m[3] - m[0] * m[5]) * id;
    inv[6] = c02 * id;
    inv[7] = (m[1] * m[6] - m[0] * m[7]) * id;
    inv[8] = (m[0] * m[4] - m[1] * m[3]) * id;
#pragma unroll
    for (int i = 0; i < 9; i++) g_cinv[s * 12 + i] = inv[i];
    g_cinv[s * 12 + 9] = 0.f; g_cinv[s * 12 + 10] = 0.f; g_cinv[s * 12 + 11] = 0.f;

    for (int j = 0; j < 32; j++) {
        float acc = b2a[j];
        const float* wr = w2a + j * 90 + 9;
#pragma unroll
        for (int p = 0; p < 9; p++) {
            float mp = m[p];
#pragma unroll
            for (int q = 0; q < 9; q++)
                acc = fmaf(wr[p * 9 + q], mp * m[q], acc);
        }
        g_cvec[s * 32 + j] = acc;
    }
}

__global__ __launch_bounds__(256) void atom_kernel(
    const float* __restrict__ atom_prop, const float* __restrict__ pos,
    const int* __restrict__ batch,
    const float* __restrict__ w0, const float* __restrict__ b0,
    const float* __restrict__ w1, const float* __restrict__ b1,
    const float* __restrict__ w1n, const float* __restrict__ b1n,
    const float* __restrict__ w2a,
    const float* __restrict__ w2b, const float* __restrict__ b2b,
    const float* __restrict__ w2c, const float* __restrict__ b2c,
    float* __restrict__ out, int n)
{
    // Transposed weights: k-major, output-index contiguous -> LDS.128 yields
    // two packed f32x2 operands per load.
    __shared__ __align__(16) float sW1t[9 * 32];   // [k][j]  w2a[:, :9]^T
    __shared__ __align__(16) float sW2t[32 * 16];  // [k][j]  w2b^T
    __shared__ __align__(16) float sW3t[16 * 8];   // [k][j]  w2c^T padded j->8
    __shared__ float sSmall[64]; // w0[9] w1[9] w1n[9] b0[3] b1[3] b1n[3] b2b[16] b2c[8(pad)]

    int tid = threadIdx.x;
    for (int i = tid; i < 288; i += blockDim.x) {
        int k = i >> 5, j = i & 31;
        sW1t[i] = w2a[j * 90 + k];
    }
    for (int i = tid; i < 512; i += blockDim.x) {
        int k = i >> 4, j = i & 15;
        sW2t[i] = w2b[j * 32 + k];
    }
    for (int i = tid; i < 128; i += blockDim.x) {
        int k = i >> 3, j = i & 7;
        sW3t[i] = (j < 6) ? w2c[j * 16 + k] : 0.f;
    }
    if (tid < 9)        sSmall[tid] = w0[tid];
    else if (tid < 18)  sSmall[tid] = w1[tid - 9];
    else if (tid < 27)  sSmall[tid] = w1n[tid - 18];
    else if (tid < 30)  sSmall[tid] = b0[tid - 27];
    else if (tid < 33)  sSmall[tid] = b1[tid - 30];
    else if (tid < 36)  sSmall[tid] = b1n[tid - 33];
    else if (tid < 52)  sSmall[tid] = b2b[tid - 36];
    else if (tid < 60)  sSmall[tid] = (tid < 58) ? b2c[tid - 52] : 0.f;
    __syncthreads();

    const float* sw0  = sSmall;
    const float* sw1  = sSmall + 9;
    const float* sw1n = sSmall + 18;
    const float* sb0  = sSmall + 27;
    const float* sb1  = sSmall + 30;
    const float* sb1n = sSmall + 33;
    const float* sb2b = sSmall + 36;
    const float* sb2c = sSmall + 52;

    int i = blockIdx.x * blockDim.x + tid;
    int lane = tid & 31;
    bool valid = i < n;
    int b = -1;
    float h3[6];
#pragma unroll
    for (int k = 0; k < 6; k++) h3[k] = 0.f;

    if (valid) {
        b = batch[i];
        float p0 = pos[3 * i], p1 = pos[3 * i + 1], p2 = pos[3 * i + 2];
        const float4* civ = (const float4*)(g_cinv + b * 12);
        float4 c0 = civ[0], c1 = civ[1], c2 = civ[2];
        float ci[9] = {c0.x, c0.y, c0.z, c0.w, c1.x, c1.y, c1.z, c1.w, c2.x};
        float th[3];
#pragma unroll
        for (int e = 0; e < 3; e++) {
            float f = fmaf(p0, ci[e], fmaf(p1, ci[3 + e], p2 * ci[6 + e]));
            th[e] = f - floorf(f) - 0.5f;
        }
        float ap0 = atom_prop[3 * i], ap1 = atom_prop[3 * i + 1], ap2 = atom_prop[3 * i + 2];

        float x[9];
        x[0] = ap0; x[1] = ap1; x[2] = ap2;
#pragma unroll
        for (int j = 0; j < 3; j++) {
            float a = leaky(fmaf(sw0[j * 3], ap0, fmaf(sw0[j * 3 + 1], ap1, fmaf(sw0[j * 3 + 2], ap2, sb0[j]))));
            float u = fmaf(sw1[j * 3], th[0], fmaf(sw1[j * 3 + 1], th[1], fmaf(sw1[j * 3 + 2], th[2], sb1[j])));
            float v = sb1n[j] - fmaf(sw1n[j * 3], th[0], fmaf(sw1n[j * 3 + 1], th[1], sw1n[j * 3 + 2] * th[2]));
            x[3 + j] = fmaxf(u, 0.f) * a;
            x[6 + j] = fmaxf(v, 0.f) * a;
        }

        // ---- layer 1: 32 outputs, 9 inputs, packed pairs ----
        unsigned long long acc1[16];
        {
            const float4* cvp = (const float4*)(g_cvec + b * 32);
#pragma unroll
            for (int p = 0; p < 8; p++) {
                float4 c = cvp[p];
                acc1[2 * p]     = pack2(c.x, c.y);
                acc1[2 * p + 1] = pack2(c.z, c.w);
            }
#pragma unroll
            for (int k = 0; k < 9; k++) {
                unsigned long long xb = pack2(x[k], x[k]);
                const ulonglong2* wr = (const ulonglong2*)(sW1t + k * 32);
#pragma unroll
                for (int p = 0; p < 8; p++) {
                    ulonglong2 w = wr[p];
                    acc1[2 * p]     = fma2(w.x, xb, acc1[2 * p]);
                    acc1[2 * p + 1] = fma2(w.y, xb, acc1[2 * p + 1]);
                }
            }
        }
        float h1[32];
#pragma unroll
        for (int p = 0; p < 16; p++) {
            float lo, hi;
            unpack2(acc1[p], lo, hi);
            h1[2 * p]     = fmaxf(lo, 0.f);
            h1[2 * p + 1] = fmaxf(hi, 0.f);
        }

        // ---- layer 2: 16 outputs, 32 inputs ----
        unsigned long long acc2[8];
#pragma unroll
        for (int p = 0; p < 8; p++) acc2[p] = pack2(sb2b[2 * p], sb2b[2 * p + 1]);
#pragma unroll
        for (int k = 0; k < 32; k++) {
            unsigned long long xb = pack2(h1[k], h1[k]);
            const ulonglong2* wr = (const ulonglong2*)(sW2t + k * 16);
#pragma unroll
            for (int p = 0; p < 4; p++) {
                ulonglong2 w = wr[p];
                acc2[2 * p]     = fma2(w.x, xb, acc2[2 * p]);
                acc2[2 * p + 1] = fma2(w.y, xb, acc2[2 * p + 1]);
            }
        }
        float h2[16];
#pragma unroll
        for (int p = 0; p < 8; p++) {
            float lo, hi;
            unpack2(acc2[p], lo, hi);
            h2[2 * p]     = leaky(lo);
            h2[2 * p + 1] = leaky(hi);
        }

        // ---- layer 3: 6 outputs (padded to 8), 16 inputs ----
        unsigned long long acc3[4];
#pragma unroll
        for (int p = 0; p < 4; p++) acc3[p] = pack2(sb2c[2 * p], sb2c[2 * p + 1]);
#pragma unroll
        for (int k = 0; k < 16; k++) {
            unsigned long long xb = pack2(h2[k], h2[k]);
            const ulonglong2* wr = (const ulonglong2*)(sW3t + k * 8);
#pragma unroll
            for (int p = 0; p < 2; p++) {
                ulonglong2 w = wr[p];
                acc3[2 * p]     = fma2(w.x, xb, acc3[2 * p]);
                acc3[2 * p + 1] = fma2(w.y, xb, acc3[2 * p + 1]);
            }
        }
        {
            float lo, hi;
            unpack2(acc3[0], lo, hi); h3[0] = lo; h3[1] = hi;
            unpack2(acc3[1], lo, hi); h3[2] = lo; h3[3] = hi;
            unpack2(acc3[2], lo, hi); h3[4] = lo; h3[5] = hi;
        }
    }

    // Segmented inclusive scan over sorted batch within the warp.
    const unsigned mask = 0xffffffffu;
#pragma unroll
    for (int d = 1; d < 32; d <<= 1) {
        int ob = __shfl_up_sync(mask, b, d);
        bool take = (lane >= d) && (ob == b);
#pragma unroll
        for (int k = 0; k < 6; k++) {
            float o = __shfl_up_sync(mask, h3[k], d);
            if (take) h3[k] += o;
        }
    }
    int nb = __shfl_down_sync(mask, b, 1);
    bool tail = (lane == 31) || (nb != b);
    if (valid && tail) {
#pragma unroll
        for (int k = 0; k < 6; k++) atomicAdd(&out[b * 6 + k], h3[k]);
    }
}

extern "C" void kernel_launch(void* const* d_in, const int* in_sizes, int n_in,
                              void* d_out, int out_size)
{
    const float* atom_prop = (const float*)d_in[0];
    const float* pos       = (const float*)d_in[1];
    const float* cell      = (const float*)d_in[2];
    const int*   batch     = (const int*)d_in[3];
    const float* w0  = (const float*)d_in[4];
    const float* b0  = (const float*)d_in[5];
    const float* w1  = (const float*)d_in[6];
    const float* b1  = (const float*)d_in[7];
    const float* w1n = (const float*)d_in[8];
    const float* b1n = (const float*)d_in[9];
    const float* w2a = (const float*)d_in[10];
    const float* b2a = (const float*)d_in[11];
    const float* w2b = (const float*)d_in[12];
    const float* b2b = (const float*)d_in[13];
    const float* w2c = (const float*)d_in[14];
    const float* b2c = (const float*)d_in[15];
    float* out = (float*)d_out;

    int n = in_sizes[3];        // N_ATOMS
    int S = in_sizes[2] / 9;    // N_STRUCT

    precompute_kernel<<<(S + 255) / 256, 256>>>(cell, w2a, b2a, out, S);
    atom_kernel<<<(n + 255) / 256, 256>>>(atom_prop, pos, batch,
                                          w0, b0, w1, b1, w1n, b1n,
                                          w2a, w2b, b2b, w2c, b2c,
                                          out, n);
}

// round 4
// speedup vs baseline: 1.7196x; 1.4996x over previous
#include <cuda_runtime.h>

#define N_STRUCT_MAX 16384

__device__ __align__(16) float g_cinv[N_STRUCT_MAX * 12];
__device__ __align__(16) float g_cvec[N_STRUCT_MAX * 32];

__device__ __forceinline__ float leaky(float x) { return x >= 0.f ? x : 0.01f * x; }

__device__ __forceinline__ unsigned long long pack2(float lo, float hi) {
    unsigned long long r;
    asm("mov.b64 %0, {%1, %2};" : "=l"(r) : "f"(lo), "f"(hi));
    return r;
}
__device__ __forceinline__ void unpack2(unsigned long long v, float& lo, float& hi) {
    asm("mov.b64 {%0, %1}, %2;" : "=f"(lo), "=f"(hi) : "l"(v));
}
__device__ __forceinline__ unsigned long long fma2(unsigned long long a, unsigned long long b,
                                                   unsigned long long c) {
    unsigned long long d;
    asm("fma.rn.f32x2 %0, %1, %2, %3;" : "=l"(d) : "l"(a), "l"(b), "l"(c));
    return d;
}

// One warp per structure. Lane j computes cvec[s*32+j]; lane 0 also does the
// 3x3 inverse; lanes 0..5 zero out[s*6..].
__global__ __launch_bounds__(256) void precompute_kernel(
    const float* __restrict__ cell,
    const float* __restrict__ w2a,
    const float* __restrict__ b2a,
    float* __restrict__ out, int S)
{
    __shared__ float sW[81 * 32];  // [t][j] = w2a[j*90+9+t]
    int tid = threadIdx.x;
    for (int i = tid; i < 81 * 32; i += blockDim.x) {
        int t = i >> 5, j = i & 31;
        sW[i] = w2a[j * 90 + 9 + t];
    }
    __syncthreads();

    int warpId = tid >> 5;
    int lane = tid & 31;
    int s = blockIdx.x * 8 + warpId;
    if (s >= S) return;

    float m[9];
#pragma unroll
    for (int i = 0; i < 9; i++) m[i] = __ldg(cell + s * 9 + i);

    float acc = b2a[lane];
#pragma unroll
    for (int p = 0; p < 9; p++) {
        float mp = m[p];
#pragma unroll
        for (int q = 0; q < 9; q++)
            acc = fmaf(sW[(p * 9 + q) * 32 + lane], mp * m[q], acc);
    }
    g_cvec[s * 32 + lane] = acc;

    if (lane < 6) out[s * 6 + lane] = 0.f;

    if (lane == 0) {
        float c00 = m[4] * m[8] - m[5] * m[7];
        float c01 = m[5] * m[6] - m[3] * m[8];
        float c02 = m[3] * m[7] - m[4] * m[6];
        float det = m[0] * c00 + m[1] * c01 + m[2] * c02;
        float id = 1.f / det;
        float4* o = (float4*)(g_cinv + s * 12);
        float4 r0, r1, r2;
        r0.x = c00 * id;
        r0.y = (m[2] * m[7] - m[1] * m[8]) * id;
        r0.z = (m[1] * m[5] - m[2] * m[4]) * id;
        r0.w = c01 * id;
        r1.x = (m[0] * m[8] - m[2] * m[6]) * id;
        r1.y = (m[2] * m[3] - m[0] * m[5]) * id;
        r1.z = c02 * id;
        r1.w = (m[1] * m[6] - m[0] * m[7]) * id;
        r2.x = (m[0] * m[4] - m[1] * m[3]) * id;
        r2.y = 0.f; r2.z = 0.f; r2.w = 0.f;
        o[0] = r0; o[1] = r1; o[2] = r2;
    }
}

// 2 atoms per thread: weight LDS amortized across both atoms.
__global__ __launch_bounds__(256) void atom_kernel(
    const float* __restrict__ atom_prop, const float* __restrict__ pos,
    const int* __restrict__ batch,
    const float* __restrict__ w0, const float* __restrict__ b0,
    const float* __restrict__ w1, const float* __restrict__ b1,
    const float* __restrict__ w1n, const float* __restrict__ b1n,
    const float* __restrict__ w2a,
    const float* __restrict__ w2b, const float* __restrict__ b2b,
    const float* __restrict__ w2c, const float* __restrict__ b2c,
    float* __restrict__ out, int n)
{
    __shared__ __align__(16) float sW1t[9 * 32];   // [k][j]
    __shared__ __align__(16) float sW2t[32 * 16];  // [k][j]
    __shared__ __align__(16) float sW3t[16 * 8];   // [k][j], j padded to 8
    __shared__ float sSmall[64];

    int tid = threadIdx.x;
    for (int i = tid; i < 288; i += blockDim.x) {
        int k = i >> 5, j = i & 31;
        sW1t[i] = w2a[j * 90 + k];
    }
    for (int i = tid; i < 512; i += blockDim.x) {
        int k = i >> 4, j = i & 15;
        sW2t[i] = w2b[j * 32 + k];
    }
    for (int i = tid; i < 128; i += blockDim.x) {
        int k = i >> 3, j = i & 7;
        sW3t[i] = (j < 6) ? w2c[j * 16 + k] : 0.f;
    }
    if (tid < 9)        sSmall[tid] = w0[tid];
    else if (tid < 18)  sSmall[tid] = w1[tid - 9];
    else if (tid < 27)  sSmall[tid] = w1n[tid - 18];
    else if (tid < 30)  sSmall[tid] = b0[tid - 27];
    else if (tid < 33)  sSmall[tid] = b1[tid - 30];
    else if (tid < 36)  sSmall[tid] = b1n[tid - 33];
    else if (tid < 52)  sSmall[tid] = b2b[tid - 36];
    else if (tid < 60)  sSmall[tid] = (tid < 58) ? b2c[tid - 52] : 0.f;
    __syncthreads();

    const float* sw0  = sSmall;
    const float* sw1  = sSmall + 9;
    const float* sw1n = sSmall + 18;
    const float* sb0  = sSmall + 27;
    const float* sb1  = sSmall + 30;
    const float* sb1n = sSmall + 33;
    const float* sb2b = sSmall + 36;
    const float* sb2c = sSmall + 52;

    int lane = tid & 31;
    int i0 = (blockIdx.x * blockDim.x + tid) * 2;
    int i1 = i0 + 1;
    bool v0 = i0 < n, v1 = i1 < n;
    int b0i = v0 ? batch[i0] : -1;
    int b1i = v1 ? batch[i1] : (v0 ? b0i : -1);

    float hA[6], hB[6];
#pragma unroll
    for (int k = 0; k < 6; k++) { hA[k] = 0.f; hB[k] = 0.f; }

    float xA[9], xB[9];
    bool anyv = v0;
    if (anyv) {
        // ---- head for both atoms ----
        const float2* pp = (const float2*)(pos + 3 * i0);
        float2 q0 = pp[0], q1 = pp[1], q2 = v1 ? pp[2] : make_float2(0.f, 0.f);
        const float2* ap = (const float2*)(atom_prop + 3 * i0);
        float2 a0 = ap[0], a1 = ap[1], a2 = v1 ? ap[2] : make_float2(0.f, 0.f);

        float pA[3] = {q0.x, q0.y, q1.x};
        float pB[3] = {q1.y, q2.x, q2.y};
        float apA[3] = {a0.x, a0.y, a1.x};
        float apB[3] = {a1.y, a2.x, a2.y};

#pragma unroll
        for (int at = 0; at < 2; at++) {
            int bb = at ? b1i : b0i;
            const float* P = at ? pB : pA;
            const float* AP = at ? apB : apA;
            float* X = at ? xB : xA;
            const float4* civ = (const float4*)(g_cinv + bb * 12);
            float4 c0 = civ[0], c1 = civ[1], c2 = civ[2];
            float ci[9] = {c0.x, c0.y, c0.z, c0.w, c1.x, c1.y, c1.z, c1.w, c2.x};
            float th[3];
#pragma unroll
            for (int e = 0; e < 3; e++) {
                float f = fmaf(P[0], ci[e], fmaf(P[1], ci[3 + e], P[2] * ci[6 + e]));
                th[e] = f - floorf(f) - 0.5f;
            }
            X[0] = AP[0]; X[1] = AP[1]; X[2] = AP[2];
#pragma unroll
            for (int j = 0; j < 3; j++) {
                float a = leaky(fmaf(sw0[j*3], AP[0], fmaf(sw0[j*3+1], AP[1], fmaf(sw0[j*3+2], AP[2], sb0[j]))));
                float u = fmaf(sw1[j*3], th[0], fmaf(sw1[j*3+1], th[1], fmaf(sw1[j*3+2], th[2], sb1[j])));
                float v = sb1n[j] - fmaf(sw1n[j*3], th[0], fmaf(sw1n[j*3+1], th[1], sw1n[j*3+2] * th[2]));
                X[3 + j] = fmaxf(u, 0.f) * a;
                X[6 + j] = fmaxf(v, 0.f) * a;
            }
        }

        // ---- layer 1 (shared weight loads feed both atoms) ----
        unsigned long long accA[16], accB[16];
        {
            const float4* cvA = (const float4*)(g_cvec + b0i * 32);
            const float4* cvB = (const float4*)(g_cvec + b1i * 32);
#pragma unroll
            for (int p = 0; p < 8; p++) {
                float4 ca = cvA[p], cb = cvB[p];
                accA[2*p]   = pack2(ca.x, ca.y);
                accA[2*p+1] = pack2(ca.z, ca.w);
                accB[2*p]   = pack2(cb.x, cb.y);
                accB[2*p+1] = pack2(cb.z, cb.w);
            }
#pragma unroll
            for (int k = 0; k < 9; k++) {
                unsigned long long xa = pack2(xA[k], xA[k]);
                unsigned long long xb = pack2(xB[k], xB[k]);
                const ulonglong2* wr = (const ulonglong2*)(sW1t + k * 32);
#pragma unroll
                for (int p = 0; p < 8; p++) {
                    ulonglong2 w = wr[p];
                    accA[2*p]   = fma2(w.x, xa, accA[2*p]);
                    accA[2*p+1] = fma2(w.y, xa, accA[2*p+1]);
                    accB[2*p]   = fma2(w.x, xb, accB[2*p]);
                    accB[2*p+1] = fma2(w.y, xb, accB[2*p+1]);
                }
            }
        }
        float h1A[32], h1B[32];
#pragma unroll
        for (int p = 0; p < 16; p++) {
            float lo, hi;
            unpack2(accA[p], lo, hi);
            h1A[2*p] = fmaxf(lo, 0.f); h1A[2*p+1] = fmaxf(hi, 0.f);
            unpack2(accB[p], lo, hi);
            h1B[2*p] = fmaxf(lo, 0.f); h1B[2*p+1] = fmaxf(hi, 0.f);
        }

        // ---- layer 2 ----
        unsigned long long acc2A[8], acc2B[8];
#pragma unroll
        for (int p = 0; p < 8; p++) {
            unsigned long long bb = pack2(sb2b[2*p], sb2b[2*p+1]);
            acc2A[p] = bb; acc2B[p] = bb;
        }
#pragma unroll
        for (int k = 0; k < 32; k++) {
            unsigned long long xa = pack2(h1A[k], h1A[k]);
            unsigned long long xb = pack2(h1B[k], h1B[k]);
            const ulonglong2* wr = (const ulonglong2*)(sW2t + k * 16);
#pragma unroll
            for (int p = 0; p < 4; p++) {
                ulonglong2 w = wr[p];
                acc2A[2*p]   = fma2(w.x, xa, acc2A[2*p]);
                acc2A[2*p+1] = fma2(w.y, xa, acc2A[2*p+1]);
                acc2B[2*p]   = fma2(w.x, xb, acc2B[2*p]);
                acc2B[2*p+1] = fma2(w.y, xb, acc2B[2*p+1]);
            }
        }
        float h2A[16], h2B[16];
#pragma unroll
        for (int p = 0; p < 8; p++) {
            float lo, hi;
            unpack2(acc2A[p], lo, hi);
            h2A[2*p] = leaky(lo); h2A[2*p+1] = leaky(hi);
            unpack2(acc2B[p], lo, hi);
            h2B[2*p] = leaky(lo); h2B[2*p+1] = leaky(hi);
        }

        // ---- layer 3 ----
        unsigned long long acc3A[4], acc3B[4];
#pragma unroll
        for (int p = 0; p < 4; p++) {
            unsigned long long bb = pack2(sb2c[2*p], sb2c[2*p+1]);
            acc3A[p] = bb; acc3B[p] = bb;
        }
#pragma unroll
        for (int k = 0; k < 16; k++) {
            unsigned long long xa = pack2(h2A[k], h2A[k]);
            unsigned long long xb = pack2(h2B[k], h2B[k]);
            const ulonglong2* wr = (const ulonglong2*)(sW3t + k * 8);
#pragma unroll
            for (int p = 0; p < 2; p++) {
                ulonglong2 w = wr[p];
                acc3A[2*p]   = fma2(w.x, xa, acc3A[2*p]);
                acc3A[2*p+1] = fma2(w.y, xa, acc3A[2*p+1]);
                acc3B[2*p]   = fma2(w.x, xb, acc3B[2*p]);
                acc3B[2*p+1] = fma2(w.y, xb, acc3B[2*p+1]);
            }
        }
#pragma unroll
        for (int p = 0; p < 3; p++) {
            unpack2(acc3A[p], hA[2*p], hA[2*p+1]);
            unpack2(acc3B[p], hB[2*p], hB[2*p+1]);
        }
        if (!v1) {
#pragma unroll
            for (int k = 0; k < 6; k++) hB[k] = 0.f;
        }
    }

    // ---- segmented reduction over sorted batch (2 atoms/thread) ----
    // Scan value: second atom's h (plus first atom's if same segment).
    float vscan[6];
    bool split = (b0i != b1i);
#pragma unroll
    for (int k = 0; k < 6; k++) vscan[k] = split ? hB[k] : (hA[k] + hB[k]);

    const unsigned mask = 0xffffffffu;
#pragma unroll
    for (int d = 1; d < 32; d <<= 1) {
        int ob = __shfl_up_sync(mask, b1i, d);
        bool take = (lane >= d) && (ob == b1i);
#pragma unroll
        for (int k = 0; k < 6; k++) {
            float o = __shfl_up_sync(mask, vscan[k], d);
            if (take) vscan[k] += o;
        }
    }

    // previous thread's scanned total + key (for carry into a split thread's first atom)
    int bprev = __shfl_up_sync(mask, b1i, 1);
    float sprev[6];
#pragma unroll
    for (int k = 0; k < 6; k++) sprev[k] = __shfl_up_sync(mask, vscan[k], 1);

    // next thread's first-atom key (to detect tail of this thread's b1 segment)
    int bnext0 = __shfl_down_sync(mask, b0i, 1);

    // Flush first atom's segment if it ends inside this thread.
    if (split && b0i >= 0) {
        bool carry = (lane > 0) && (bprev == b0i);
#pragma unroll
        for (int k = 0; k < 6; k++) {
            float t = hA[k] + (carry ? sprev[k] : 0.f);
            atomicAdd(&out[b0i * 6 + k], t);
        }
    }
    // Flush scanned b1 segment at its tail.
    bool tail = (lane == 31) || (bnext0 != b1i);
    if (b1i >= 0 && tail) {
#pragma unroll
        for (int k = 0; k < 6; k++) atomicAdd(&out[b1i * 6 + k], vscan[k]);
    }
}

extern "C" void kernel_launch(void* const* d_in, const int* in_sizes, int n_in,
                              void* d_out, int out_size)
{
    const float* atom_prop = (const float*)d_in[0];
    const float* pos       = (const float*)d_in[1];
    const float* cell      = (const float*)d_in[2];
    const int*   batch     = (const int*)d_in[3];
    const float* w0  = (const float*)d_in[4];
    const float* b0  = (const float*)d_in[5];
    const float* w1  = (const float*)d_in[6];
    const float* b1  = (const float*)d_in[7];
    const float* w1n = (const float*)d_in[8];
    const float* b1n = (const float*)d_in[9];
    const float* w2a = (const float*)d_in[10];
    const float* b2a = (const float*)d_in[11];
    const float* w2b = (const float*)d_in[12];
    const float* b2b = (const float*)d_in[13];
    const float* w2c = (const float*)d_in[14];
    const float* b2c = (const float*)d_in[15];
    float* out = (float*)d_out;

    int n = in_sizes[3];        // N_ATOMS
    int S = in_sizes[2] / 9;    // N_STRUCT

    precompute_kernel<<<(S + 7) / 8, 256>>>(cell, w2a, b2a, out, S);
    int atomsPerBlock = 512;
    atom_kernel<<<(n + atomsPerBlock - 1) / atomsPerBlock, 256>>>(
        atom_prop, pos, batch, w0, b0, w1, b1, w1n, b1n,
        w2a, w2b, b2b, w2c, b2c, out, n);
}

// round 5
// speedup vs baseline: 1.9231x; 1.1184x over previous
#include <cuda_runtime.h>

#define N_STRUCT_MAX 16384

__device__ __align__(16) float g_cinv[N_STRUCT_MAX * 12];
__device__ __align__(16) float g_cvec[N_STRUCT_MAX * 32];

__device__ __forceinline__ float leaky(float x) { return x >= 0.f ? x : 0.01f * x; }

__device__ __forceinline__ unsigned long long pack2(float lo, float hi) {
    unsigned long long r;
    asm("mov.b64 %0, {%1, %2};" : "=l"(r) : "f"(lo), "f"(hi));
    return r;
}
__device__ __forceinline__ void unpack2(unsigned long long v, float& lo, float& hi) {
    asm("mov.b64 {%0, %1}, %2;" : "=f"(lo), "=f"(hi) : "l"(v));
}
__device__ __forceinline__ unsigned long long fma2(unsigned long long a, unsigned long long b,
                                                   unsigned long long c) {
    unsigned long long d;
    asm("fma.rn.f32x2 %0, %1, %2, %3;" : "=l"(d) : "l"(a), "l"(b), "l"(c));
    return d;
}

// One warp per structure.
__global__ __launch_bounds__(256) void precompute_kernel(
    const float* __restrict__ cell,
    const float* __restrict__ w2a,
    const float* __restrict__ b2a,
    float* __restrict__ out, int S)
{
    __shared__ float sW[81 * 32];  // [t][j] = w2a[j*90+9+t]
    int tid = threadIdx.x;
    for (int i = tid; i < 81 * 32; i += blockDim.x) {
        int t = i >> 5, j = i & 31;
        sW[i] = w2a[j * 90 + 9 + t];
    }
    __syncthreads();

    int warpId = tid >> 5;
    int lane = tid & 31;
    int s = blockIdx.x * 8 + warpId;
    if (s >= S) return;

    float m[9];
#pragma unroll
    for (int i = 0; i < 9; i++) m[i] = __ldg(cell + s * 9 + i);

    float acc = b2a[lane];
#pragma unroll
    for (int p = 0; p < 9; p++) {
        float mp = m[p];
#pragma unroll
        for (int q = 0; q < 9; q++)
            acc = fmaf(sW[(p * 9 + q) * 32 + lane], mp * m[q], acc);
    }
    g_cvec[s * 32 + lane] = acc;

    if (lane < 6) out[s * 6 + lane] = 0.f;

    if (lane == 0) {
        float c00 = m[4] * m[8] - m[5] * m[7];
        float c01 = m[5] * m[6] - m[3] * m[8];
        float c02 = m[3] * m[7] - m[4] * m[6];
        float det = m[0] * c00 + m[1] * c01 + m[2] * c02;
        float id = 1.f / det;
        float4* o = (float4*)(g_cinv + s * 12);
        float4 r0, r1, r2;
        r0.x = c00 * id;
        r0.y = (m[2] * m[7] - m[1] * m[8]) * id;
        r0.z = (m[1] * m[5] - m[2] * m[4]) * id;
        r0.w = c01 * id;
        r1.x = (m[0] * m[8] - m[2] * m[6]) * id;
        r1.y = (m[2] * m[3] - m[0] * m[5]) * id;
        r1.z = c02 * id;
        r1.w = (m[1] * m[6] - m[0] * m[7]) * id;
        r2.x = (m[0] * m[4] - m[1] * m[3]) * id;
        r2.y = 0.f; r2.z = 0.f; r2.w = 0.f;
        o[0] = r0; o[1] = r1; o[2] = r2;
    }
}

// 2 atoms per thread, layers fused to minimize live registers.
__global__ void __launch_bounds__(128, 5) atom_kernel(
    const float* __restrict__ atom_prop, const float* __restrict__ pos,
    const int* __restrict__ batch,
    const float* __restrict__ w0, const float* __restrict__ b0,
    const float* __restrict__ w1, const float* __restrict__ b1,
    const float* __restrict__ w1n, const float* __restrict__ b1n,
    const float* __restrict__ w2a,
    const float* __restrict__ w2b, const float* __restrict__ b2b,
    const float* __restrict__ w2c, const float* __restrict__ b2c,
    float* __restrict__ out, int n)
{
    __shared__ __align__(16) float sW1t[9 * 32];   // [k][j]
    __shared__ __align__(16) float sW2t[32 * 16];  // [k][j]
    __shared__ __align__(16) float sW3t[16 * 8];   // [k][j], j padded to 8
    __shared__ float sSmall[64];

    int tid = threadIdx.x;
    for (int i = tid; i < 288; i += blockDim.x) {
        int k = i >> 5, j = i & 31;
        sW1t[i] = w2a[j * 90 + k];
    }
    for (int i = tid; i < 512; i += blockDim.x) {
        int k = i >> 4, j = i & 15;
        sW2t[i] = w2b[j * 32 + k];
    }
    for (int i = tid; i < 128; i += blockDim.x) {
        int k = i >> 3, j = i & 7;
        sW3t[i] = (j < 6) ? w2c[j * 16 + k] : 0.f;
    }
    if (tid < 9)        sSmall[tid] = w0[tid];
    else if (tid < 18)  sSmall[tid] = w1[tid - 9];
    else if (tid < 27)  sSmall[tid] = w1n[tid - 18];
    else if (tid < 30)  sSmall[tid] = b0[tid - 27];
    else if (tid < 33)  sSmall[tid] = b1[tid - 30];
    else if (tid < 36)  sSmall[tid] = b1n[tid - 33];
    else if (tid < 52)  sSmall[tid] = b2b[tid - 36];
    else if (tid < 60)  sSmall[tid] = (tid < 58) ? b2c[tid - 52] : 0.f;
    __syncthreads();

    const float* sw0  = sSmall;
    const float* sw1  = sSmall + 9;
    const float* sw1n = sSmall + 18;
    const float* sb0  = sSmall + 27;
    const float* sb1  = sSmall + 30;
    const float* sb1n = sSmall + 33;
    const float* sb2b = sSmall + 36;
    const float* sb2c = sSmall + 52;

    int lane = tid & 31;
    int i0 = (blockIdx.x * blockDim.x + tid) * 2;
    int i1 = i0 + 1;
    bool v0 = i0 < n, v1 = i1 < n;
    int b0i, b1i;
    if (v1) {
        int2 bb = *(const int2*)(batch + i0);
        b0i = bb.x; b1i = bb.y;
    } else if (v0) {
        b0i = batch[i0]; b1i = b0i;
    } else {
        b0i = -1; b1i = -1;
    }

    float hA[6], hB[6];
#pragma unroll
    for (int k = 0; k < 6; k++) { hA[k] = 0.f; hB[k] = 0.f; }

    if (v0) {
        // ---- head ----
        const float2* pp = (const float2*)(pos + 3 * i0);
        float2 q0 = pp[0], q1 = pp[1], q2 = v1 ? pp[2] : make_float2(0.f, 0.f);
        const float2* ap = (const float2*)(atom_prop + 3 * i0);
        float2 a0 = ap[0], a1 = ap[1], a2 = v1 ? ap[2] : make_float2(0.f, 0.f);

        float pA[3] = {q0.x, q0.y, q1.x};
        float pB[3] = {q1.y, q2.x, q2.y};
        float apA[3] = {a0.x, a0.y, a1.x};
        float apB[3] = {a1.y, a2.x, a2.y};

        float xA[9], xB[9];
#pragma unroll
        for (int at = 0; at < 2; at++) {
            int bb = at ? b1i : b0i;
            const float* P = at ? pB : pA;
            const float* AP = at ? apB : apA;
            float* X = at ? xB : xA;
            const float4* civ = (const float4*)(g_cinv + bb * 12);
            float4 c0 = civ[0], c1 = civ[1], c2 = civ[2];
            float ci[9] = {c0.x, c0.y, c0.z, c0.w, c1.x, c1.y, c1.z, c1.w, c2.x};
            float th[3];
#pragma unroll
            for (int e = 0; e < 3; e++) {
                float f = fmaf(P[0], ci[e], fmaf(P[1], ci[3 + e], P[2] * ci[6 + e]));
                th[e] = f - floorf(f) - 0.5f;
            }
            X[0] = AP[0]; X[1] = AP[1]; X[2] = AP[2];
#pragma unroll
            for (int j = 0; j < 3; j++) {
                float a = leaky(fmaf(sw0[j*3], AP[0], fmaf(sw0[j*3+1], AP[1], fmaf(sw0[j*3+2], AP[2], sb0[j]))));
                float u = fmaf(sw1[j*3], th[0], fmaf(sw1[j*3+1], th[1], fmaf(sw1[j*3+2], th[2], sb1[j])));
                float v = sb1n[j] - fmaf(sw1n[j*3], th[0], fmaf(sw1n[j*3+1], th[1], sw1n[j*3+2] * th[2]));
                X[3 + j] = fmaxf(u, 0.f) * a;
                X[6 + j] = fmaxf(v, 0.f) * a;
            }
        }

        // ---- layer-2 accumulators (persistent across layer-1 tiles) ----
        unsigned long long acc2A[8], acc2B[8];
#pragma unroll
        for (int q = 0; q < 8; q++) {
            unsigned long long bb = pack2(sb2b[2*q], sb2b[2*q+1]);
            acc2A[q] = bb; acc2B[q] = bb;
        }

        // ---- layer 1 in two 16-output tiles, fused into layer 2 ----
#pragma unroll
        for (int jt = 0; jt < 2; jt++) {
            unsigned long long a1A[8], a1B[8];
            const float4* cvA = (const float4*)(g_cvec + b0i * 32) + jt * 4;
            const float4* cvB = (const float4*)(g_cvec + b1i * 32) + jt * 4;
#pragma unroll
            for (int q = 0; q < 4; q++) {
                float4 ca = cvA[q], cb = cvB[q];
                a1A[2*q]   = pack2(ca.x, ca.y);
                a1A[2*q+1] = pack2(ca.z, ca.w);
                a1B[2*q]   = pack2(cb.x, cb.y);
                a1B[2*q+1] = pack2(cb.z, cb.w);
            }
#pragma unroll
            for (int k = 0; k < 9; k++) {
                unsigned long long xa = pack2(xA[k], xA[k]);
                unsigned long long xb = pack2(xB[k], xB[k]);
                const ulonglong2* wr = (const ulonglong2*)(sW1t + k * 32 + jt * 16);
#pragma unroll
                for (int q = 0; q < 4; q++) {
                    ulonglong2 w = wr[q];
                    a1A[2*q]   = fma2(w.x, xa, a1A[2*q]);
                    a1A[2*q+1] = fma2(w.y, xa, a1A[2*q+1]);
                    a1B[2*q]   = fma2(w.x, xb, a1B[2*q]);
                    a1B[2*q+1] = fma2(w.y, xb, a1B[2*q+1]);
                }
            }
            // fuse: relu(h1 pair) -> layer 2 accumulation, a1 regs die here
#pragma unroll
            for (int p = 0; p < 8; p++) {
                float lA0, lA1, lB0, lB1;
                unpack2(a1A[p], lA0, lA1);
                unpack2(a1B[p], lB0, lB1);
                lA0 = fmaxf(lA0, 0.f); lA1 = fmaxf(lA1, 0.f);
                lB0 = fmaxf(lB0, 0.f); lB1 = fmaxf(lB1, 0.f);
                int k0 = jt * 16 + 2 * p;
#pragma unroll
                for (int r = 0; r < 2; r++) {
                    unsigned long long xa = pack2(r ? lA1 : lA0, r ? lA1 : lA0);
                    unsigned long long xb = pack2(r ? lB1 : lB0, r ? lB1 : lB0);
                    const ulonglong2* wr = (const ulonglong2*)(sW2t + (k0 + r) * 16);
#pragma unroll
                    for (int q = 0; q < 4; q++) {
                        ulonglong2 w = wr[q];
                        acc2A[2*q]   = fma2(w.x, xa, acc2A[2*q]);
                        acc2A[2*q+1] = fma2(w.y, xa, acc2A[2*q+1]);
                        acc2B[2*q]   = fma2(w.x, xb, acc2B[2*q]);
                        acc2B[2*q+1] = fma2(w.y, xb, acc2B[2*q+1]);
                    }
                }
            }
        }

        // ---- layer 3 fused from acc2 ----
        unsigned long long acc3A[4], acc3B[4];
#pragma unroll
        for (int q = 0; q < 4; q++) {
            unsigned long long bb = pack2(sb2c[2*q], sb2c[2*q+1]);
            acc3A[q] = bb; acc3B[q] = bb;
        }
#pragma unroll
        for (int p = 0; p < 8; p++) {
            float lA0, lA1, lB0, lB1;
            unpack2(acc2A[p], lA0, lA1);
            unpack2(acc2B[p], lB0, lB1);
            lA0 = leaky(lA0); lA1 = leaky(lA1);
            lB0 = leaky(lB0); lB1 = leaky(lB1);
#pragma unroll
            for (int r = 0; r < 2; r++) {
                unsigned long long xa = pack2(r ? lA1 : lA0, r ? lA1 : lA0);
                unsigned long long xb = pack2(r ? lB1 : lB0, r ? lB1 : lB0);
                const ulonglong2* wr = (const ulonglong2*)(sW3t + (2 * p + r) * 8);
#pragma unroll
                for (int q = 0; q < 2; q++) {
                    ulonglong2 w = wr[q];
                    acc3A[2*q]   = fma2(w.x, xa, acc3A[2*q]);
                    acc3A[2*q+1] = fma2(w.y, xa, acc3A[2*q+1]);
                    acc3B[2*q]   = fma2(w.x, xb, acc3B[2*q]);
                    acc3B[2*q+1] = fma2(w.y, xb, acc3B[2*q+1]);
                }
            }
        }
#pragma unroll
        for (int p = 0; p < 3; p++) {
            unpack2(acc3A[p], hA[2*p], hA[2*p+1]);
            unpack2(acc3B[p], hB[2*p], hB[2*p+1]);
        }
        if (!v1) {
#pragma unroll
            for (int k = 0; k < 6; k++) hB[k] = 0.f;
        }
    }

    // ---- segmented reduction over sorted batch (2 atoms/thread) ----
    float vscan[6];
    bool split = (b0i != b1i);
#pragma unroll
    for (int k = 0; k < 6; k++) vscan[k] = split ? hB[k] : (hA[k] + hB[k]);

    const unsigned mask = 0xffffffffu;
    unsigned mseg = __match_any_sync(mask, b1i);
    int head = __ffs(mseg) - 1;   // first lane in this warp with key b1i
#pragma unroll
    for (int d = 1; d < 32; d <<= 1) {
        bool take = (lane >= head + d);
#pragma unroll
        for (int k = 0; k < 6; k++) {
            float o = __shfl_up_sync(mask, vscan[k], d);
            if (take) vscan[k] += o;
        }
    }

    int bprev = __shfl_up_sync(mask, b1i, 1);
    float sprev[6];
#pragma unroll
    for (int k = 0; k < 6; k++) sprev[k] = __shfl_up_sync(mask, vscan[k], 1);
    int bnext0 = __shfl_down_sync(mask, b0i, 1);

    if (split && b0i >= 0) {
        bool carry = (lane > 0) && (bprev == b0i);
#pragma unroll
        for (int k = 0; k < 6; k++) {
            float t = hA[k] + (carry ? sprev[k] : 0.f);
            atomicAdd(&out[b0i * 6 + k], t);
        }
    }
    bool tail = (lane == 31) || (bnext0 != b1i);
    if (b1i >= 0 && tail) {
#pragma unroll
        for (int k = 0; k < 6; k++) atomicAdd(&out[b1i * 6 + k], vscan[k]);
    }
}

extern "C" void kernel_launch(void* const* d_in, const int* in_sizes, int n_in,
                              void* d_out, int out_size)
{
    const float* atom_prop = (const float*)d_in[0];
    const float* pos       = (const float*)d_in[1];
    const float* cell      = (const float*)d_in[2];
    const int*   batch     = (const int*)d_in[3];
    const float* w0  = (const float*)d_in[4];
    const float* b0  = (const float*)d_in[5];
    const float* w1  = (const float*)d_in[6];
    const float* b1  = (const float*)d_in[7];
    const float* w1n = (const float*)d_in[8];
    const float* b1n = (const float*)d_in[9];
    const float* w2a = (const float*)d_in[10];
    const float* b2a = (const float*)d_in[11];
    const float* w2b = (const float*)d_in[12];
    const float* b2b = (const float*)d_in[13];
    const float* w2c = (const float*)d_in[14];
    const float* b2c = (const float*)d_in[15];
    float* out = (float*)d_out;

    int n = in_sizes[3];        // N_ATOMS
    int S = in_sizes[2] / 9;    // N_STRUCT

    precompute_kernel<<<(S + 7) / 8, 256>>>(cell, w2a, b2a, out, S);
    atom_kernel<<<(n + 255) / 256, 128>>>(
        atom_prop, pos, batch, w0, b0, w1, b1, w1n, b1n,
        w2a, w2b, b2b, w2c, b2c, out, n);
}